// round 13
// baseline (speedup 1.0000x reference)
#include <cuda_runtime.h>
#include <cuda_bf16.h>

// QuantumCBOW: B=16384, S=10, DIM=8, TRIL=36.
// R13 = R12 (2 lanes/element, split Cholesky, one-sided Jacobi) with the two
// measured overheads removed:
//  * swap-based tournament: 28 pairs/sweep via 14 LOCAL rotations + two
//    2-column exchanges (36 shfl/sweep vs 144) + one lane-conditional
//    register swap (~68 SEL). All rotations two-resident -> no cross-lane
//    rotation consistency needed.
//  * 64-thread blocks (512 blocks) for even SM load; __launch_bounds__(64,6).

#define QC_DIM  8
#define QC_TRIL 36
#define QC_S    10

__device__ __forceinline__ constexpr int sidx(int i, int j) { return i * (i + 1) / 2 + j; }

// Accumulate wgt * normalized-density(row) into acc[36] (lower-tri storage).
__device__ __forceinline__ void add_density(const float* __restrict__ row, float* acc, float wgt) {
    float L[QC_TRIL];
    const float4* r4 = reinterpret_cast<const float4*>(row);  // 36*4B rows, 16B aligned
#pragma unroll
    for (int v = 0; v < 9; v++) {
        float4 t = r4[v];
        L[4 * v + 0] = t.x; L[4 * v + 1] = t.y;
        L[4 * v + 2] = t.z; L[4 * v + 3] = t.w;
    }
#pragma unroll
    for (int i = 0; i < QC_DIM; i++) {
        const int d = sidx(i, i);
        L[d] = fmaxf(L[d], 1e-4f);
    }
    float tr = 0.f;
#pragma unroll
    for (int i = 0; i < QC_TRIL; i++) tr = fmaf(L[i], L[i], tr);
    const float inv = wgt * __fdividef(1.0f, tr + 1.7e-5f);
#pragma unroll
    for (int i = 0; i < QC_DIM; i++) {
#pragma unroll
        for (int j = 0; j <= i; j++) {
            float s = 0.f;
#pragma unroll
            for (int k = 0; k <= j; k++)
                s = fmaf(L[sidx(i, k)], L[sidx(j, k)], s);
            if (i == j) s += 2e-6f;  // eps + corr
            acc[sidx(i, j)] = fmaf(s, inv, acc[sidx(i, j)]);
        }
    }
}

// Full local one-sided rotation of resident columns a[A], a[Bq] (R5/R12-validated).
#define JR(A, Bq) do {                                                         \
    float g = 0.f;                                                             \
    _Pragma("unroll")                                                          \
    for (int k = 0; k < QC_DIM; k++) g = fmaf(a[A][k], a[Bq][k], g);           \
    const float dd = n[Bq] - n[A];                                             \
    const float a2 = 2.0f * g;                                                 \
    const float vv = fmaf(dd, dd, fmaf(a2, a2, 1e-30f));                       \
    const float u  = vv * rsqrtf(vv);                                          \
    const float t  = __fdividef(a2 * copysignf(1.0f, dd), fabsf(dd) + u);      \
    const float c  = rsqrtf(fmaf(t, t, 1.0f));                                 \
    const float s  = t * c;                                                    \
    _Pragma("unroll")                                                          \
    for (int k = 0; k < QC_DIM; k++) {                                         \
        const float x = a[A][k], y = a[Bq][k];                                 \
        a[A][k]  = fmaf(c, x, -s * y);                                         \
        a[Bq][k] = fmaf(s, x,  c * y);                                         \
    }                                                                          \
    n[A]  = fmaf(-t, g, n[A]);                                                 \
    n[Bq] = fmaf( t, g, n[Bq]);                                                \
} while (0)

// Exchange slots r2,r3 (+norms) with the partner lane.
#define XCH23() do {                                                           \
    _Pragma("unroll")                                                          \
    for (int k = 0; k < QC_DIM; k++) {                                         \
        a[2][k] = __shfl_xor_sync(0xffffffffu, a[2][k], 1);                    \
        a[3][k] = __shfl_xor_sync(0xffffffffu, a[3][k], 1);                    \
    }                                                                          \
    n[2] = __shfl_xor_sync(0xffffffffu, n[2], 1);                              \
    n[3] = __shfl_xor_sync(0xffffffffu, n[3], 1);                              \
} while (0)

// On lane h==1 only: local swap (r0<->r2), (r1<->r3) (+norms). SELs, no shfl.
#define CSWAP() do {                                                           \
    _Pragma("unroll")                                                          \
    for (int k = 0; k < QC_DIM; k++) {                                         \
        const float x0 = a[0][k], y0 = a[2][k];                                \
        a[0][k] = h ? y0 : x0;  a[2][k] = h ? x0 : y0;                         \
        const float x1 = a[1][k], y1 = a[3][k];                                \
        a[1][k] = h ? y1 : x1;  a[3][k] = h ? x1 : y1;                         \
    }                                                                          \
    { const float x = n[0], y = n[2]; n[0] = h ? y : x; n[2] = h ? x : y; }    \
    { const float x = n[1], y = n[3]; n[1] = h ? y : x; n[3] = h ? x : y; }    \
} while (0)

__global__ void __launch_bounds__(64, 6)
qcbow_kernel(const int* __restrict__ contexts,
             const int* __restrict__ targets,
             const float* __restrict__ emb,
             float* __restrict__ out,
             int B) {
    const int gt = blockIdx.x * 64 + threadIdx.x;
    const int e = gt >> 1;
    const int h = gt & 1;
    if (e >= B) return;   // 2B % 64 == 0 -> no partial pairs/warps in practice

    // ---- token ids (row is 8B-aligned: 10 ints = 5 x int2) ----
    int toks[QC_S];
    {
        const int2* c2 = reinterpret_cast<const int2*>(contexts + e * QC_S);
#pragma unroll
        for (int v = 0; v < 5; v++) {
            const int2 t = c2[v];
            toks[2 * v] = t.x; toks[2 * v + 1] = t.y;
        }
    }
    const int tgt = targets[e];

    // ---- sigma density (both lanes; same row -> L1 broadcast) ----
    float sigm[QC_TRIL];
#pragma unroll
    for (int i = 0; i < QC_TRIL; i++) sigm[i] = 0.f;
    add_density(emb + (long)tgt * QC_TRIL, sigm, 1.0f);

    // ---- 5 context densities for this lane: tokens {2k + h} ----
    float ctxp[QC_TRIL];
#pragma unroll
    for (int i = 0; i < QC_TRIL; i++) ctxp[i] = 0.f;
    float cnt = 0.f;
#pragma unroll
    for (int k = 0; k < 5; k++) {
        const int tok = toks[2 * k + h];
        const float m = (tok != 0) ? 1.0f : 0.0f;
        cnt += m;
        add_density(emb + (long)tok * QC_TRIL, ctxp, m);
    }

    // ---- butterfly: full ctx + cnt across the lane pair ----
    cnt += __shfl_xor_sync(0xffffffffu, cnt, 1);
#pragma unroll
    for (int i = 0; i < QC_TRIL; i++)
        ctxp[i] += __shfl_xor_sync(0xffffffffu, ctxp[i], 1);
    const float ic = __fdividef(1.0f, cnt);  // cnt==0 -> inf, matches ref 0/0

    // ---- my Cholesky target: h0 -> ctx/cnt + 1e-6 I, h1 -> sigma ----
    float mat[QC_TRIL];
#pragma unroll
    for (int i = 0; i < QC_TRIL; i++) {
        const float cv = ctxp[i] * ic;
        mat[i] = h ? sigm[i] : cv;
    }
    const float dadd = h ? 0.0f : 1e-6f;
#pragma unroll
    for (int d = 0; d < QC_DIM; d++) mat[sidx(d, d)] += dadd;

    // ---- in-place Cholesky of mat (uniform code, per-lane data) ----
#pragma unroll
    for (int j = 0; j < QC_DIM; j++) {
        float d = mat[sidx(j, j)];
#pragma unroll
        for (int k = 0; k < j; k++) d = fmaf(-mat[sidx(j, k)], mat[sidx(j, k)], d);
        d = fmaxf(d, 1e-20f);
        const float icjj = rsqrtf(d);
        mat[sidx(j, j)] = d * icjj;
#pragma unroll
        for (int i = j + 1; i < QC_DIM; i++) {
            float v = mat[sidx(i, j)];
#pragma unroll
            for (int k = 0; k < j; k++) v = fmaf(-mat[sidx(i, k)], mat[sidx(j, k)], v);
            mat[sidx(i, j)] = v * icjj;
        }
    }
    // h0: mat = C (CC^T = ctx+1e-6I); h1: mat = S (SS^T = sigma)

    // ---- factor exchange + materialize S, C ----
    float S[QC_TRIL], C[QC_TRIL];
#pragma unroll
    for (int i = 0; i < QC_TRIL; i++) {
        const float o = __shfl_xor_sync(0xffffffffu, mat[i], 1);
        S[i] = h ? mat[i] : o;
        C[i] = h ? o : mat[i];
    }

    // ---- my 4 columns of A = S^T C  (cols 4h .. 4h+3), column-at-a-time ----
    float a[4][QC_DIM];
#pragma unroll
    for (int jj = 0; jj < 4; jj++) {
        float Cc[QC_DIM];   // C[k][4h+jj], zero-padded k<col (compile-time idx + SEL)
#pragma unroll
        for (int k = 0; k < QC_DIM; k++) {
            const float v0 = (k >= jj)     ? C[(k >= jj)     ? sidx(k, jj)     : 0] : 0.f;
            const float v1 = (k >= jj + 4) ? C[(k >= jj + 4) ? sidx(k, jj + 4) : 0] : 0.f;
            Cc[k] = h ? v1 : v0;
        }
#pragma unroll
        for (int i = 0; i < QC_DIM; i++) {
            float s = 0.f;
#pragma unroll
            for (int k = i; k < QC_DIM; k++)
                s = fmaf(S[sidx(k, i)], Cc[k], s);
            a[jj][i] = s;
        }
    }

    // ---- one-sided Jacobi: swap-based tournament, 3 sweeps x 28 pairs ----
    float n[4];
#pragma unroll 1
    for (int sweep = 0; sweep < 3; sweep++) {
        // fresh norms each sweep
#pragma unroll
        for (int jj = 0; jj < 4; jj++) {
            float s = 0.f;
#pragma unroll
            for (int k = 0; k < QC_DIM; k++) s = fmaf(a[jj][k], a[jj][k], s);
            n[jj] = s;
        }
        // P1: all 6 within-set pairs (3 rounds of 2 independent rotations)
        JR(0, 1); JR(2, 3);
        JR(0, 2); JR(1, 3);
        JR(0, 3); JR(1, 2);
        // X1 + P2: 4 cross pairs
        XCH23();
        JR(0, 2); JR(1, 3);
        JR(0, 3); JR(1, 2);
        // lane-1 local swap + X2 + P3: remaining 4 cross pairs
        CSWAP();
        XCH23();
        JR(0, 2); JR(1, 3);
        JR(0, 3); JR(1, 2);
    }

    // ---- f = sum sqrt(colnorm^2 + eps) over all 8 cols (perm-invariant) ----
    float p = 0.f;
#pragma unroll
    for (int jj = 0; jj < 4; jj++) {
        float s = 0.f;
#pragma unroll
        for (int k = 0; k < QC_DIM; k++) s = fmaf(a[jj][k], a[jj][k], s);
        const float x = s + 1e-6f;
        p = fmaf(x, rsqrtf(x), p);   // sqrt(x) = x*rsqrt(x)
    }
    p += __shfl_xor_sync(0xffffffffu, p, 1);
    if (h == 0) {
        float f = fminf(p, 1.0f);
        f = fmaxf(f, 1e-8f);
        out[e] = -logf(f);
    }
}

extern "C" void kernel_launch(void* const* d_in, const int* in_sizes, int n_in,
                              void* d_out, int out_size) {
    const int*   contexts = (const int*)d_in[0];   // [B, 10] int32
    const int*   targets  = (const int*)d_in[1];   // [B] int32
    const float* emb      = (const float*)d_in[2]; // [V, 36] float32
    float*       out      = (float*)d_out;         // [B] float32
    const int B = in_sizes[1];                     // 16384
    const int threads = 64;
    const int blocks = (2 * B + threads - 1) / threads;   // 512 blocks
    qcbow_kernel<<<blocks, threads>>>(contexts, targets, emb, out, B);
}